// round 14
// baseline (speedup 1.0000x reference)
#include <cuda_runtime.h>
#include <cuda_bf16.h>
#include <cstdint>

#define B_ 16
#define P_ 16
#define D_ 128
#define F_ 128
#define C_ 1024
#define BP 256
#define YS 8            // y-splits per (b,p) in k_score
#define CPB (C_ / YS)   // 128 candidates per block

// ---------------- scratch (no allocations allowed) ----------------
__device__ float d_exp[B_ * P_ * C_];    // exp(score) (0 for masked)
__device__ float d_psum[BP * YS];        // per-block partial sums (deterministic order)

// ---------------- Kernel 1: candidate scores -> exp + partial sums ----------------
// score[b,p,c] = cand_emb[b,p,c,:] . score_w[D+2F : D+2F+D]  for c < cand_len[b,p]
// The per-b additive terms of the reference (query/v1/v2/score_b chain) are constant
// along the per-b softmax axis and cancel; masked entries are exp->0 in both.
// Scores are O(1) (weights are 0.02-scaled), so exp without max-shift is safe and
// softmax is shift-invariant => identical result.
//
// grid (BP, YS) x 256 threads: warp per candidate row (32 x float4 = 512B coalesced).
__global__ void k_score(const float* __restrict__ cand, const int* __restrict__ clen,
                        const float* __restrict__ sw) {
    int bp = blockIdx.x;
    int cbeg = blockIdx.y * CPB;
    int warp = threadIdx.x >> 5, lane = threadIdx.x & 31;
    __shared__ float4 ws[32];
    __shared__ float wsum[8];
    if (threadIdx.x < 32) ws[threadIdx.x] = ((const float4*)(sw + D_ + 2 * F_))[threadIdx.x];
    int len = clen[bp];
    __syncthreads();
    float4 w = ws[lane];
    const float4* cbase = (const float4*)cand + (size_t)bp * C_ * 32;
    float* erow = d_exp + (size_t)bp * C_;
    float acc = 0.f;
    #pragma unroll 4
    for (int cc = warp; cc < CPB; cc += 8) {
        int c = cbeg + cc;
        if (c < len) {
            float4 v = cbase[c * 32 + lane];
            float s = v.x * w.x + v.y * w.y + v.z * w.z + v.w * w.w;
            #pragma unroll
            for (int off = 16; off; off >>= 1) s += __shfl_xor_sync(0xffffffffu, s, off);
            float e = __expf(s);
            if (lane == 0) erow[c] = e;
            acc += e;                      // same value in all lanes; lane 0's copy is used
        } else if (lane == 0) {
            erow[c] = 0.f;
        }
    }
    if (lane == 0) wsum[warp] = acc;
    __syncthreads();
    if (threadIdx.x == 0) {
        float s = 0.f;
        #pragma unroll
        for (int i = 0; i < 8; i++) s += wsum[i];   // fixed order: deterministic
        d_psum[bp * YS + blockIdx.y] = s;
    }
}

// ---------------- Kernel 2: reduce partials + normalize ----------------
// grid (B_, 8) x 256 threads; block handles 2048 outputs of batch b.
// Partials for b are d_psum[b*128 .. b*128+127] (contiguous).
__global__ void k_norm(float* __restrict__ out) {
    int b = blockIdx.x, chunk = blockIdx.y;
    int t = threadIdx.x;  // 0..255
    __shared__ float red[128];
    if (t < 128) red[t] = d_psum[b * 128 + t];
    __syncthreads();
    #pragma unroll
    for (int off = 64; off > 0; off >>= 1) {
        if (t < off) red[t] += red[t + off];
        __syncthreads();
    }
    float inv = 1.f / red[0];
    const float4* e4 = (const float4*)(d_exp + (size_t)b * (P_ * C_) + chunk * 2048);
    float4* o4 = (float4*)(out + (size_t)b * (P_ * C_) + chunk * 2048);
    #pragma unroll
    for (int i = t; i < 512; i += 256) {
        float4 v = e4[i];
        v.x *= inv; v.y *= inv; v.z *= inv; v.w *= inv;
        o4[i] = v;
    }
}

// ---------------- launch ----------------
extern "C" void kernel_launch(void* const* d_in, const int* in_sizes, int n_in,
                              void* d_out, int out_size) {
    const float* cand_emb = (const float*)d_in[3];
    const int*   cand_len = (const int*)d_in[4];
    const float* score_w  = (const float*)d_in[19];
    float* out = (float*)d_out;

    k_score<<<dim3(BP, YS), 256>>>(cand_emb, cand_len, score_w);
    k_norm<<<dim3(B_, 8), 256>>>(out);
}